// round 1
// baseline (speedup 1.0000x reference)
#include <cuda_runtime.h>
#include <cstdint>

#define NEG 1000000000000.0f

// Scratch: Q/K after projection + RoPE, layout [B][HEADS][L][64] fp32.
// 16*12*512*64 = 6,291,456 floats = 25.2 MB each.
__device__ float g_Q[16 * 12 * 512 * 64];
__device__ float g_K[16 * 12 * 512 * 64];

// ---------------------------------------------------------------------------
// Kernel 1: C[8192,1536] = A[8192,1024] @ W[1024,1536] + b, fused RoPE epilogue
// writing into g_Q / g_K with [b][h][l][d] layout.
// Tile: BM=128, BN=128, BK=16, 256 threads, 8x8 micro-tile per thread.
// ---------------------------------------------------------------------------
__global__ __launch_bounds__(256) void proj_rope_kernel(
    const float* __restrict__ A,      // [8192,1024]
    const float* __restrict__ W,      // [1024,1536]
    const float* __restrict__ bias,   // [1536]
    const float* __restrict__ pe)     // [512,64] pos_emb
{
    __shared__ float As[16][128];   // [k][m] (transposed)
    __shared__ float Bs[16][128];   // [k][n]

    const int tid = threadIdx.x;
    const int tx = tid & 15;        // 0..15 (N direction)
    const int ty = tid >> 4;        // 0..15 (M direction)
    const int bm = blockIdx.y * 128;  // gridDim.y = 64
    const int bn = blockIdx.x * 128;  // gridDim.x = 12

    float acc[8][8] = {};

    for (int k0 = 0; k0 < 1024; k0 += 16) {
        // Load A tile: 128 rows x 16 cols = 512 float4, 2 per thread.
#pragma unroll
        for (int r = 0; r < 2; ++r) {
            int idx = tid + r * 256;
            int row = idx >> 2;            // 0..127
            int c4  = (idx & 3) * 4;       // 0,4,8,12
            float4 v = *(const float4*)&A[(size_t)(bm + row) * 1024 + k0 + c4];
            As[c4 + 0][row] = v.x;
            As[c4 + 1][row] = v.y;
            As[c4 + 2][row] = v.z;
            As[c4 + 3][row] = v.w;
        }
        // Load W tile: 16 rows x 128 cols = 512 float4, 2 per thread.
#pragma unroll
        for (int r = 0; r < 2; ++r) {
            int idx = tid + r * 256;
            int row = idx >> 5;            // 0..15
            int c4  = (idx & 31) * 4;      // 0..124
            *(float4*)&Bs[row][c4] =
                *(const float4*)&W[(size_t)(k0 + row) * 1536 + bn + c4];
        }
        __syncthreads();

#pragma unroll
        for (int k = 0; k < 16; ++k) {
            float a[8], bb[8];
#pragma unroll
            for (int i = 0; i < 8; ++i) a[i]  = As[k][ty * 8 + i];
#pragma unroll
            for (int j = 0; j < 8; ++j) bb[j] = Bs[k][tx * 8 + j];
#pragma unroll
            for (int i = 0; i < 8; ++i)
#pragma unroll
                for (int j = 0; j < 8; ++j)
                    acc[i][j] = fmaf(a[i], bb[j], acc[i][j]);
        }
        __syncthreads();
    }

    // Epilogue: bias + RoPE + scatter into g_Q/g_K.
    const int jbase = bn + tx * 8;     // aligned to 8, never crosses h or q/k boundary
    const int h  = jbase / 128;
    const int c  = jbase % 128;
    const bool isK = (c >= 64);
    const int dd = isK ? (c - 64) : c; // 0..56, multiple of 8
    float* dst = isK ? g_K : g_Q;

    float bv[8];
#pragma unroll
    for (int j = 0; j < 8; ++j) bv[j] = bias[jbase + j];

#pragma unroll
    for (int i = 0; i < 8; ++i) {
        const int m = bm + ty * 8 + i;
        const int l = m & 511;
        const int bidx = m >> 9;
        const float* per = pe + l * 64;

        float v[8];
#pragma unroll
        for (int j = 0; j < 8; ++j) v[j] = acc[i][j] + bv[j];

        float res[8];
#pragma unroll
        for (int p = 0; p < 4; ++p) {
            int pi = (dd >> 1) + p;          // pair index within head dim
            float s  = per[2 * pi];          // sin
            float ct = per[2 * pi + 1];      // cos
            float e = v[2 * p], o = v[2 * p + 1];
            res[2 * p]     = e * ct - o * s;
            res[2 * p + 1] = o * ct + e * s;
        }

        float* base = dst + ((((size_t)bidx * 12 + h) * 512 + l) * 64 + dd);
        *(float4*)(base)     = make_float4(res[0], res[1], res[2], res[3]);
        *(float4*)(base + 4) = make_float4(res[4], res[5], res[6], res[7]);
    }
}

// ---------------------------------------------------------------------------
// Kernel 2: per (b,h): logits[512,512] = Q[512,64] @ K[512,64]^T with fused
// padding mask, strict-lower-triangular -NEG, and 0.125 scale.
// Tile: 128x128, K chunks of 32 (two iters), 256 threads, 8x8 micro-tile.
// ---------------------------------------------------------------------------
__global__ __launch_bounds__(256) void qk_logits_kernel(
    const int* __restrict__ mask,   // [16,512]
    float* __restrict__ out)        // [16,12,512,512]
{
    __shared__ float Qs[32][128];   // [k][m]
    __shared__ float Ks[32][128];   // [k][n]

    const int bh = blockIdx.z;              // 0..191
    const int b  = bh / 12;
    const float* Qp = g_Q + (size_t)bh * 512 * 64;
    const float* Kp = g_K + (size_t)bh * 512 * 64;

    const int bm = blockIdx.y * 128;
    const int bn = blockIdx.x * 128;
    const int tid = threadIdx.x;
    const int tx = tid & 15;
    const int ty = tid >> 4;

    float acc[8][8] = {};

    for (int k0 = 0; k0 < 64; k0 += 32) {
        // Each tile: 128 rows x 32 cols = 1024 float4; 4 per thread per tensor.
#pragma unroll
        for (int r = 0; r < 4; ++r) {
            int idx = tid + r * 256;
            int row = idx >> 3;             // 0..127
            int c4  = (idx & 7) * 4;        // 0..28
            float4 q = *(const float4*)&Qp[(size_t)(bm + row) * 64 + k0 + c4];
            Qs[c4 + 0][row] = q.x; Qs[c4 + 1][row] = q.y;
            Qs[c4 + 2][row] = q.z; Qs[c4 + 3][row] = q.w;
            float4 k = *(const float4*)&Kp[(size_t)(bn + row) * 64 + k0 + c4];
            Ks[c4 + 0][row] = k.x; Ks[c4 + 1][row] = k.y;
            Ks[c4 + 2][row] = k.z; Ks[c4 + 3][row] = k.w;
        }
        __syncthreads();

#pragma unroll
        for (int k = 0; k < 32; ++k) {
            float a[8], bb[8];
#pragma unroll
            for (int i = 0; i < 8; ++i) a[i]  = Qs[k][ty * 8 + i];
#pragma unroll
            for (int j = 0; j < 8; ++j) bb[j] = Ks[k][tx * 8 + j];
#pragma unroll
            for (int i = 0; i < 8; ++i)
#pragma unroll
                for (int j = 0; j < 8; ++j)
                    acc[i][j] = fmaf(a[i], bb[j], acc[i][j]);
        }
        __syncthreads();
    }

    // Epilogue: mask over n, strict lower-tri -NEG, scale by 0.125.
    const int* mb = mask + b * 512;
    float mv[8];
#pragma unroll
    for (int j = 0; j < 8; ++j) mv[j] = (float)mb[bn + tx * 8 + j];

#pragma unroll
    for (int i = 0; i < 8; ++i) {
        const int m = bm + ty * 8 + i;
        float r[8];
#pragma unroll
        for (int j = 0; j < 8; ++j) {
            const int n = bn + tx * 8 + j;
            float v = acc[i][j] * mv[j] - (1.0f - mv[j]) * NEG;
            if (m > n) v -= NEG;
            r[j] = v * 0.125f;
        }
        float* op = out + (((size_t)bh * 512 + m) * 512 + (bn + tx * 8));
        *(float4*)(op)     = make_float4(r[0], r[1], r[2], r[3]);
        *(float4*)(op + 4) = make_float4(r[4], r[5], r[6], r[7]);
    }
}

extern "C" void kernel_launch(void* const* d_in, const int* in_sizes, int n_in,
                              void* d_out, int out_size) {
    const float* inputs = (const float*)d_in[0];   // [16,512,1024]
    const int*   mask   = (const int*)d_in[1];     // [16,512]
    const float* W      = (const float*)d_in[2];   // [1024,1536]
    const float* bias   = (const float*)d_in[3];   // [1536]
    const float* pe     = (const float*)d_in[4];   // [512,64]
    float* out = (float*)d_out;                    // [16,12,512,512]

    (void)in_sizes; (void)n_in; (void)out_size;

    proj_rope_kernel<<<dim3(12, 64), 256>>>(inputs, W, bias, pe);
    qk_logits_kernel<<<dim3(4, 4, 192), 256>>>(mask, out);
}

// round 2
// speedup vs baseline: 1.0002x; 1.0002x over previous
#include <cuda_runtime.h>
#include <cstdint>

#define NEG 1000000000000.0f

// Scratch: Q/K after projection + RoPE, layout [B][HEADS][L][64] fp32.
// 16*12*512*64 = 6,291,456 floats = 25.2 MB each.
__device__ float g_Q[16 * 12 * 512 * 64];
__device__ float g_K[16 * 12 * 512 * 64];

// ---------------------------------------------------------------------------
// Kernel 1: C[8192,1536] = A[8192,1024] @ W[1024,1536] + b, fused RoPE epilogue
// writing into g_Q / g_K with [b][h][l][d] layout.
// Tile: BM=128, BN=128, BK=16, 256 threads, 8x8 micro-tile per thread.
// ---------------------------------------------------------------------------
__global__ __launch_bounds__(256) void proj_rope_kernel(
    const float* __restrict__ A,      // [8192,1024]
    const float* __restrict__ W,      // [1024,1536]
    const float* __restrict__ bias,   // [1536]
    const float* __restrict__ pe)     // [512,64] pos_emb
{
    __shared__ float As[16][128];   // [k][m] (transposed)
    __shared__ float Bs[16][128];   // [k][n]

    const int tid = threadIdx.x;
    const int tx = tid & 15;        // 0..15 (N direction)
    const int ty = tid >> 4;        // 0..15 (M direction)
    const int bm = blockIdx.y * 128;  // gridDim.y = 64
    const int bn = blockIdx.x * 128;  // gridDim.x = 12

    float acc[8][8] = {};

    for (int k0 = 0; k0 < 1024; k0 += 16) {
        // Load A tile: 128 rows x 16 cols = 512 float4, 2 per thread.
#pragma unroll
        for (int r = 0; r < 2; ++r) {
            int idx = tid + r * 256;
            int row = idx >> 2;            // 0..127
            int c4  = (idx & 3) * 4;       // 0,4,8,12
            float4 v = *(const float4*)&A[(size_t)(bm + row) * 1024 + k0 + c4];
            As[c4 + 0][row] = v.x;
            As[c4 + 1][row] = v.y;
            As[c4 + 2][row] = v.z;
            As[c4 + 3][row] = v.w;
        }
        // Load W tile: 16 rows x 128 cols = 512 float4, 2 per thread.
#pragma unroll
        for (int r = 0; r < 2; ++r) {
            int idx = tid + r * 256;
            int row = idx >> 5;            // 0..15
            int c4  = (idx & 31) * 4;      // 0..124
            *(float4*)&Bs[row][c4] =
                *(const float4*)&W[(size_t)(k0 + row) * 1536 + bn + c4];
        }
        __syncthreads();

#pragma unroll
        for (int k = 0; k < 16; ++k) {
            float a[8], bb[8];
#pragma unroll
            for (int i = 0; i < 8; ++i) a[i]  = As[k][ty * 8 + i];
#pragma unroll
            for (int j = 0; j < 8; ++j) bb[j] = Bs[k][tx * 8 + j];
#pragma unroll
            for (int i = 0; i < 8; ++i)
#pragma unroll
                for (int j = 0; j < 8; ++j)
                    acc[i][j] = fmaf(a[i], bb[j], acc[i][j]);
        }
        __syncthreads();
    }

    // Epilogue: bias + RoPE + scatter into g_Q/g_K.
    const int jbase = bn + tx * 8;     // aligned to 8, never crosses h or q/k boundary
    const int h  = jbase / 128;
    const int c  = jbase % 128;
    const bool isK = (c >= 64);
    const int dd = isK ? (c - 64) : c; // 0..56, multiple of 8
    float* dst = isK ? g_K : g_Q;

    float bv[8];
#pragma unroll
    for (int j = 0; j < 8; ++j) bv[j] = bias[jbase + j];

#pragma unroll
    for (int i = 0; i < 8; ++i) {
        const int m = bm + ty * 8 + i;
        const int l = m & 511;
        const int bidx = m >> 9;
        const float* per = pe + l * 64;

        float v[8];
#pragma unroll
        for (int j = 0; j < 8; ++j) v[j] = acc[i][j] + bv[j];

        float res[8];
#pragma unroll
        for (int p = 0; p < 4; ++p) {
            int pi = (dd >> 1) + p;          // pair index within head dim
            float s  = per[2 * pi];          // sin
            float ct = per[2 * pi + 1];      // cos
            float e = v[2 * p], o = v[2 * p + 1];
            res[2 * p]     = e * ct - o * s;
            res[2 * p + 1] = o * ct + e * s;
        }

        float* base = dst + ((((size_t)bidx * 12 + h) * 512 + l) * 64 + dd);
        *(float4*)(base)     = make_float4(res[0], res[1], res[2], res[3]);
        *(float4*)(base + 4) = make_float4(res[4], res[5], res[6], res[7]);
    }
}

// ---------------------------------------------------------------------------
// Kernel 2: per (b,h): logits[512,512] = Q[512,64] @ K[512,64]^T with fused
// padding mask, strict-lower-triangular -NEG, and 0.125 scale.
// Tile: 128x128, K chunks of 32 (two iters), 256 threads, 8x8 micro-tile.
// ---------------------------------------------------------------------------
__global__ __launch_bounds__(256) void qk_logits_kernel(
    const int* __restrict__ mask,   // [16,512]
    float* __restrict__ out)        // [16,12,512,512]
{
    __shared__ float Qs[32][128];   // [k][m]
    __shared__ float Ks[32][128];   // [k][n]

    const int bh = blockIdx.z;              // 0..191
    const int b  = bh / 12;
    const float* Qp = g_Q + (size_t)bh * 512 * 64;
    const float* Kp = g_K + (size_t)bh * 512 * 64;

    const int bm = blockIdx.y * 128;
    const int bn = blockIdx.x * 128;
    const int tid = threadIdx.x;
    const int tx = tid & 15;
    const int ty = tid >> 4;

    float acc[8][8] = {};

    for (int k0 = 0; k0 < 64; k0 += 32) {
        // Each tile: 128 rows x 32 cols = 1024 float4; 4 per thread per tensor.
#pragma unroll
        for (int r = 0; r < 4; ++r) {
            int idx = tid + r * 256;
            int row = idx >> 3;             // 0..127
            int c4  = (idx & 7) * 4;        // 0..28
            float4 q = *(const float4*)&Qp[(size_t)(bm + row) * 64 + k0 + c4];
            Qs[c4 + 0][row] = q.x; Qs[c4 + 1][row] = q.y;
            Qs[c4 + 2][row] = q.z; Qs[c4 + 3][row] = q.w;
            float4 k = *(const float4*)&Kp[(size_t)(bn + row) * 64 + k0 + c4];
            Ks[c4 + 0][row] = k.x; Ks[c4 + 1][row] = k.y;
            Ks[c4 + 2][row] = k.z; Ks[c4 + 3][row] = k.w;
        }
        __syncthreads();

#pragma unroll
        for (int k = 0; k < 32; ++k) {
            float a[8], bb[8];
#pragma unroll
            for (int i = 0; i < 8; ++i) a[i]  = Qs[k][ty * 8 + i];
#pragma unroll
            for (int j = 0; j < 8; ++j) bb[j] = Ks[k][tx * 8 + j];
#pragma unroll
            for (int i = 0; i < 8; ++i)
#pragma unroll
                for (int j = 0; j < 8; ++j)
                    acc[i][j] = fmaf(a[i], bb[j], acc[i][j]);
        }
        __syncthreads();
    }

    // Epilogue: mask over n, strict lower-tri -NEG, scale by 0.125.
    const int* mb = mask + b * 512;
    float mv[8];
#pragma unroll
    for (int j = 0; j < 8; ++j) mv[j] = (float)mb[bn + tx * 8 + j];

#pragma unroll
    for (int i = 0; i < 8; ++i) {
        const int m = bm + ty * 8 + i;
        float r[8];
#pragma unroll
        for (int j = 0; j < 8; ++j) {
            const int n = bn + tx * 8 + j;
            float v = acc[i][j] * mv[j] - (1.0f - mv[j]) * NEG;
            if (m > n) v -= NEG;
            r[j] = v * 0.125f;
        }
        float* op = out + (((size_t)bh * 512 + m) * 512 + (bn + tx * 8));
        *(float4*)(op)     = make_float4(r[0], r[1], r[2], r[3]);
        *(float4*)(op + 4) = make_float4(r[4], r[5], r[6], r[7]);
    }
}

extern "C" void kernel_launch(void* const* d_in, const int* in_sizes, int n_in,
                              void* d_out, int out_size) {
    const float* inputs = (const float*)d_in[0];   // [16,512,1024]
    const int*   mask   = (const int*)d_in[1];     // [16,512]
    const float* W      = (const float*)d_in[2];   // [1024,1536]
    const float* bias   = (const float*)d_in[3];   // [1536]
    const float* pe     = (const float*)d_in[4];   // [512,64]
    float* out = (float*)d_out;                    // [16,12,512,512]

    (void)in_sizes; (void)n_in; (void)out_size;

    proj_rope_kernel<<<dim3(12, 64), 256>>>(inputs, W, bias, pe);
    qk_logits_kernel<<<dim3(4, 4, 192), 256>>>(mask, out);
}

// round 3
// speedup vs baseline: 3.0192x; 3.0186x over previous
#include <cuda_runtime.h>
#include <cuda_bf16.h>
#include <cstdint>

#define NEG 1000000000000.0f

// Q/K after projection + RoPE, stored as bf16 pairs (uint32 = bf16x2).
// Layout: [B*HEADS][512][32] uint32  (= [bh][l][64] bf16). 12.6 MB each.
__device__ uint32_t g_Qh[192 * 512 * 32];
__device__ uint32_t g_Kh[192 * 512 * 32];

// ---------------------------------------------------------------------------
// helpers
// ---------------------------------------------------------------------------
__device__ __forceinline__ uint32_t pack_bf16x2(float lo, float hi) {
    uint32_t r;
    asm("cvt.rn.bf16x2.f32 %0, %1, %2;" : "=r"(r) : "f"(hi), "f"(lo));
    return r;
}

__device__ __forceinline__ void ldsm_x4(uint32_t& r0, uint32_t& r1,
                                        uint32_t& r2, uint32_t& r3, uint32_t addr) {
    asm volatile("ldmatrix.sync.aligned.m8n8.x4.shared.b16 {%0,%1,%2,%3}, [%4];"
                 : "=r"(r0), "=r"(r1), "=r"(r2), "=r"(r3) : "r"(addr));
}

__device__ __forceinline__ void ldsm_x4_t(uint32_t& r0, uint32_t& r1,
                                          uint32_t& r2, uint32_t& r3, uint32_t addr) {
    asm volatile("ldmatrix.sync.aligned.m8n8.x4.trans.shared.b16 {%0,%1,%2,%3}, [%4];"
                 : "=r"(r0), "=r"(r1), "=r"(r2), "=r"(r3) : "r"(addr));
}

__device__ __forceinline__ void mma_bf16(float* c, const uint32_t* a, const uint32_t* b) {
    asm volatile(
        "mma.sync.aligned.m16n8k16.row.col.f32.bf16.bf16.f32 "
        "{%0,%1,%2,%3}, {%4,%5,%6,%7}, {%8,%9}, {%0,%1,%2,%3};"
        : "+f"(c[0]), "+f"(c[1]), "+f"(c[2]), "+f"(c[3])
        : "r"(a[0]), "r"(a[1]), "r"(a[2]), "r"(a[3]), "r"(b[0]), "r"(b[1]));
}

// ---------------------------------------------------------------------------
// Kernel 1: C[8192,1536] = A[8192,1024] @ W[1024,1536] + b  (bf16 mma, fp32 acc)
// fused RoPE epilogue, writes bf16 Q/K in [bh][l][64] layout.
// Block: 128x128 tile (one head per N-block), BK=32, 256 threads (8 warps 2x4).
// ---------------------------------------------------------------------------
#define PA 40    // A smem pitch (bf16 elems): 80B rows -> conflict-free ldmatrix
#define PW 136   // W smem pitch: 272B rows -> conflict-free ldmatrix

__global__ __launch_bounds__(256) void proj_rope_kernel(
    const float* __restrict__ A,      // [8192,1024]
    const float* __restrict__ W,      // [1024,1536]
    const float* __restrict__ bias,   // [1536]
    const float* __restrict__ pe)     // [512,64]
{
    __shared__ __align__(16) uint16_t As[128 * PA];
    __shared__ __align__(16) uint16_t Ws[32 * PW];

    const int tid = threadIdx.x;
    const int lane = tid & 31;
    const int wid = tid >> 5;
    const int warp_m = wid >> 2;      // 0..1
    const int warp_n = wid & 3;       // 0..3
    const int h  = blockIdx.x;        // 0..11 (head)
    const int bn = h * 128;
    const int bm = blockIdx.y * 128;

    float acc[4][4][4] = {};

    const uint32_t As_b = (uint32_t)__cvta_generic_to_shared(As);
    const uint32_t Ws_b = (uint32_t)__cvta_generic_to_shared(Ws);

    // per-lane ldmatrix address components
    const int a_row_l = warp_m * 64 + (lane & 15);      // + mtile*16
    const int a_col_l = (lane & 16) ? 8 : 0;            // + kk
    const int b_krow_l = lane & 15;                     // + kk
    const int b_ncol_l = warp_n * 32 + ((lane & 16) ? 8 : 0);  // + npair*16

    for (int k0 = 0; k0 < 1024; k0 += 32) {
        // ---- load A tile 128x32 fp32 -> bf16 smem
#pragma unroll
        for (int r = 0; r < 2; ++r) {
            int chunk = tid + r * 256;          // 512 chunks of 8 floats
            int row = chunk >> 2;
            int kg  = chunk & 3;
            const float4* p = (const float4*)&A[(size_t)(bm + row) * 1024 + k0 + kg * 8];
            float4 v0 = p[0], v1 = p[1];
            uint4 u;
            u.x = pack_bf16x2(v0.x, v0.y);
            u.y = pack_bf16x2(v0.z, v0.w);
            u.z = pack_bf16x2(v1.x, v1.y);
            u.w = pack_bf16x2(v1.z, v1.w);
            *(uint4*)&As[row * PA + kg * 8] = u;
        }
        // ---- load W tile 32x128 fp32 -> bf16 smem
#pragma unroll
        for (int r = 0; r < 2; ++r) {
            int chunk = tid + r * 256;
            int kr = chunk >> 4;
            int ng = chunk & 15;
            const float4* p = (const float4*)&W[(size_t)(k0 + kr) * 1536 + bn + ng * 8];
            float4 v0 = p[0], v1 = p[1];
            uint4 u;
            u.x = pack_bf16x2(v0.x, v0.y);
            u.y = pack_bf16x2(v0.z, v0.w);
            u.z = pack_bf16x2(v1.x, v1.y);
            u.w = pack_bf16x2(v1.z, v1.w);
            *(uint4*)&Ws[kr * PW + ng * 8] = u;
        }
        __syncthreads();

#pragma unroll
        for (int kk = 0; kk < 32; kk += 16) {
            uint32_t af[4][4];
#pragma unroll
            for (int mt = 0; mt < 4; ++mt) {
                uint32_t addr = As_b + ((a_row_l + mt * 16) * PA + kk + a_col_l) * 2;
                ldsm_x4(af[mt][0], af[mt][1], af[mt][2], af[mt][3], addr);
            }
            uint32_t bf[4][2];
#pragma unroll
            for (int np = 0; np < 2; ++np) {
                uint32_t addr = Ws_b + ((kk + b_krow_l) * PW + b_ncol_l + np * 16) * 2;
                ldsm_x4_t(bf[2 * np][0], bf[2 * np][1],
                          bf[2 * np + 1][0], bf[2 * np + 1][1], addr);
            }
#pragma unroll
            for (int mt = 0; mt < 4; ++mt)
#pragma unroll
                for (int nt = 0; nt < 4; ++nt)
                    mma_bf16(acc[mt][nt], af[mt], bf[nt]);
        }
        __syncthreads();
    }

    // ---- epilogue: bias + RoPE -> bf16 Q/K
    const int g = lane >> 2, t = lane & 3;
    const bool isK = (warp_n >= 2);
    uint32_t* dst = isK ? g_Kh : g_Qh;
    const int dbase = (warp_n & 1) * 32;

    float be[4], bo[4];
    int pi[4];
#pragma unroll
    for (int nt = 0; nt < 4; ++nt) {
        int jb = bn + warp_n * 32 + nt * 8 + 2 * t;
        be[nt] = bias[jb];
        bo[nt] = bias[jb + 1];
        pi[nt] = (dbase + nt * 8 + 2 * t) >> 1;
    }

    const float2* pe2 = (const float2*)pe;

#pragma unroll
    for (int mt = 0; mt < 4; ++mt) {
#pragma unroll
        for (int rr = 0; rr < 2; ++rr) {
            int m = bm + warp_m * 64 + mt * 16 + g + 8 * rr;
            int l = m & 511;
            int b = m >> 9;
            size_t rowbase = ((size_t)(b * 12 + h) * 512 + l) * 32;
#pragma unroll
            for (int nt = 0; nt < 4; ++nt) {
                float2 sc = pe2[l * 32 + pi[nt]];   // x=sin, y=cos
                float e = acc[mt][nt][2 * rr]     + be[nt];
                float o = acc[mt][nt][2 * rr + 1] + bo[nt];
                float re = e * sc.y - o * sc.x;
                float ro = o * sc.y + e * sc.x;
                dst[rowbase + pi[nt]] = pack_bf16x2(re, ro);
            }
        }
    }
}

// ---------------------------------------------------------------------------
// Kernel 2: per (b,h): logits[512,512] = Q @ K^T (bf16 mma), fused mask/tril/scale.
// Block: 128x128 tile, K=64 resident, 256 threads (8 warps 2x4).
// ---------------------------------------------------------------------------
#define PQ 72    // smem pitch (bf16): 144B rows -> conflict-free ldmatrix

__global__ __launch_bounds__(256) void qk_logits_kernel(
    const int* __restrict__ mask,   // [16,512]
    float* __restrict__ out)        // [16,12,512,512]
{
    __shared__ __align__(16) uint16_t Qs[128 * PQ];
    __shared__ __align__(16) uint16_t Ks[128 * PQ];

    const int tid = threadIdx.x;
    const int lane = tid & 31;
    const int wid = tid >> 5;
    const int warp_m = wid >> 2;
    const int warp_n = wid & 3;
    const int bh = blockIdx.z;
    const int b  = bh / 12;
    const int bm = blockIdx.y * 128;
    const int bn = blockIdx.x * 128;

    // ---- load Q/K tiles (bf16, 128x64 each)
    const uint4* Qg = (const uint4*)(g_Qh + ((size_t)bh * 512 + bm) * 32);
    const uint4* Kg = (const uint4*)(g_Kh + ((size_t)bh * 512 + bn) * 32);
#pragma unroll
    for (int r = 0; r < 4; ++r) {
        int chunk = tid + r * 256;       // 1024 chunks of 8 bf16
        int row = chunk >> 3;
        int kg  = chunk & 7;
        *(uint4*)&Qs[row * PQ + kg * 8] = Qg[row * 8 + kg];
        *(uint4*)&Ks[row * PQ + kg * 8] = Kg[row * 8 + kg];
    }
    __syncthreads();

    const uint32_t Qs_b = (uint32_t)__cvta_generic_to_shared(Qs);
    const uint32_t Ks_b = (uint32_t)__cvta_generic_to_shared(Ks);

    const int a_row_l = warp_m * 64 + (lane & 15);
    const int a_col_l = (lane & 16) ? 8 : 0;
    // B (non-trans) lane mapping: rows = n, cols = k
    const int b_row_l = warp_n * 32 + (lane & 7) + ((lane & 16) >> 1);
    const int b_col_l = (lane & 8) ? 8 : 0;

    float acc[4][4][4] = {};

#pragma unroll
    for (int ks = 0; ks < 4; ++ks) {
        int k = ks * 16;
        uint32_t af[4][4];
#pragma unroll
        for (int mt = 0; mt < 4; ++mt) {
            uint32_t addr = Qs_b + ((a_row_l + mt * 16) * PQ + k + a_col_l) * 2;
            ldsm_x4(af[mt][0], af[mt][1], af[mt][2], af[mt][3], addr);
        }
        uint32_t bf[4][2];
#pragma unroll
        for (int np = 0; np < 2; ++np) {
            uint32_t addr = Ks_b + ((b_row_l + np * 16) * PQ + k + b_col_l) * 2;
            ldsm_x4(bf[2 * np][0], bf[2 * np][1],
                    bf[2 * np + 1][0], bf[2 * np + 1][1], addr);
        }
#pragma unroll
        for (int mt = 0; mt < 4; ++mt)
#pragma unroll
            for (int nt = 0; nt < 4; ++nt)
                mma_bf16(acc[mt][nt], af[mt], bf[nt]);
    }

    // ---- epilogue: padding mask, strict lower-tri, scale 0.125
    const int g = lane >> 2, t = lane & 3;
    const int* mb = mask + b * 512;
    float mv0[4], mv1[4];
    int ncol[4];
#pragma unroll
    for (int nt = 0; nt < 4; ++nt) {
        int n = bn + warp_n * 32 + nt * 8 + 2 * t;
        ncol[nt] = n;
        mv0[nt] = (float)mb[n];
        mv1[nt] = (float)mb[n + 1];
    }

#pragma unroll
    for (int mt = 0; mt < 4; ++mt) {
#pragma unroll
        for (int rr = 0; rr < 2; ++rr) {
            int m = bm + warp_m * 64 + mt * 16 + g + 8 * rr;
            size_t rowbase = ((size_t)bh * 512 + m) * 512;
#pragma unroll
            for (int nt = 0; nt < 4; ++nt) {
                int n = ncol[nt];
                float v0 = acc[mt][nt][2 * rr]     * mv0[nt] - (1.0f - mv0[nt]) * NEG;
                float v1 = acc[mt][nt][2 * rr + 1] * mv1[nt] - (1.0f - mv1[nt]) * NEG;
                if (m > n)     v0 -= NEG;
                if (m > n + 1) v1 -= NEG;
                float2 res = make_float2(v0 * 0.125f, v1 * 0.125f);
                *(float2*)&out[rowbase + n] = res;
            }
        }
    }
}

extern "C" void kernel_launch(void* const* d_in, const int* in_sizes, int n_in,
                              void* d_out, int out_size) {
    const float* inputs = (const float*)d_in[0];   // [16,512,1024]
    const int*   mask   = (const int*)d_in[1];     // [16,512]
    const float* W      = (const float*)d_in[2];   // [1024,1536]
    const float* bias   = (const float*)d_in[3];   // [1536]
    const float* pe     = (const float*)d_in[4];   // [512,64]
    float* out = (float*)d_out;                    // [16,12,512,512]

    (void)in_sizes; (void)n_in; (void)out_size;

    proj_rope_kernel<<<dim3(12, 64), 256>>>(inputs, W, bias, pe);
    qk_logits_kernel<<<dim3(4, 4, 192), 256>>>(mask, out);
}

// round 4
// speedup vs baseline: 5.1793x; 1.7154x over previous
#include <cuda_runtime.h>
#include <cuda_bf16.h>
#include <cstdint>

#define NEG 1000000000000.0f

// bf16 copies of A and W (pre-pass output), stored as bf16x2 in uint32.
__device__ uint32_t g_Ah[8192 * 512];   // [8192][1024] bf16, 16 MB
__device__ uint32_t g_Wh[1024 * 768];   // [1024][1536] bf16, 3 MB
// Q/K after projection + RoPE: [bh][l][64] bf16. 12.6 MB each.
__device__ uint32_t g_Qh[192 * 512 * 32];
__device__ uint32_t g_Kh[192 * 512 * 32];

// ---------------------------------------------------------------------------
// helpers
// ---------------------------------------------------------------------------
__device__ __forceinline__ uint32_t pack_bf16x2(float lo, float hi) {
    uint32_t r;
    asm("cvt.rn.bf16x2.f32 %0, %1, %2;" : "=r"(r) : "f"(hi), "f"(lo));
    return r;
}

__device__ __forceinline__ void ldsm_x4(uint32_t& r0, uint32_t& r1,
                                        uint32_t& r2, uint32_t& r3, uint32_t addr) {
    asm volatile("ldmatrix.sync.aligned.m8n8.x4.shared.b16 {%0,%1,%2,%3}, [%4];"
                 : "=r"(r0), "=r"(r1), "=r"(r2), "=r"(r3) : "r"(addr));
}

__device__ __forceinline__ void ldsm_x4_t(uint32_t& r0, uint32_t& r1,
                                          uint32_t& r2, uint32_t& r3, uint32_t addr) {
    asm volatile("ldmatrix.sync.aligned.m8n8.x4.trans.shared.b16 {%0,%1,%2,%3}, [%4];"
                 : "=r"(r0), "=r"(r1), "=r"(r2), "=r"(r3) : "r"(addr));
}

__device__ __forceinline__ void mma_bf16(float* c, const uint32_t* a, const uint32_t* b) {
    asm volatile(
        "mma.sync.aligned.m16n8k16.row.col.f32.bf16.bf16.f32 "
        "{%0,%1,%2,%3}, {%4,%5,%6,%7}, {%8,%9}, {%0,%1,%2,%3};"
        : "+f"(c[0]), "+f"(c[1]), "+f"(c[2]), "+f"(c[3])
        : "r"(a[0]), "r"(a[1]), "r"(a[2]), "r"(a[3]), "r"(b[0]), "r"(b[1]));
}

__device__ __forceinline__ void cp_async8(uint32_t smem_addr, const void* gptr) {
    asm volatile("cp.async.ca.shared.global [%0], [%1], 8;"
                 :: "r"(smem_addr), "l"(gptr));
}
#define CP_COMMIT() asm volatile("cp.async.commit_group;" ::: "memory")
#define CP_WAIT1()  asm volatile("cp.async.wait_group 1;" ::: "memory")

// ---------------------------------------------------------------------------
// Pre-pass: fp32 -> bf16 for A and W.
// ---------------------------------------------------------------------------
__global__ __launch_bounds__(256) void convert_kernel(
    const float* __restrict__ A, const float* __restrict__ W)
{
    const size_t nA = (size_t)8192 * 1024 / 4;   // float4 count
    size_t i = (size_t)blockIdx.x * 256 + threadIdx.x;
    if (i < nA) {
        float4 v = ((const float4*)A)[i];
        uint2 u;
        u.x = pack_bf16x2(v.x, v.y);
        u.y = pack_bf16x2(v.z, v.w);
        ((uint2*)g_Ah)[i] = u;
    } else {
        size_t j = i - nA;                        // < 1024*1536/4
        float4 v = ((const float4*)W)[j];
        uint2 u;
        u.x = pack_bf16x2(v.x, v.y);
        u.y = pack_bf16x2(v.z, v.w);
        ((uint2*)g_Wh)[j] = u;
    }
}

// ---------------------------------------------------------------------------
// Kernel 1: C[8192,1536] = A @ W + b (bf16 mma, fp32 acc), 3-stage cp.async
// pipeline, fused RoPE epilogue -> bf16 Q/K in [bh][l][64].
// Block: 128x128 tile, BK=32, 256 threads (8 warps 2x4).
// ---------------------------------------------------------------------------
#define PA 40    // A smem pitch (bf16): 80B rows, conflict-free ldmatrix
#define PW 136   // W smem pitch: 272B rows, conflict-free ldmatrix.trans
#define ASZ (128 * PA)                 // 5120 elems
#define STG_ELEMS (ASZ + 32 * PW)      // 5120 + 4352 = 9472 elems (18944 B)

__global__ __launch_bounds__(256) void proj_rope_kernel(
    const float* __restrict__ bias,   // [1536]
    const float* __restrict__ pe)     // [512,64]
{
    __shared__ __align__(16) uint16_t smem[3 * STG_ELEMS];

    const int tid = threadIdx.x;
    const int lane = tid & 31;
    const int wid = tid >> 5;
    const int warp_m = wid >> 2;      // 0..1
    const int warp_n = wid & 3;       // 0..3
    const int h  = blockIdx.x;        // head 0..11
    const int bn = h * 128;
    const int bm = blockIdx.y * 128;

    const uint32_t smem_b = (uint32_t)__cvta_generic_to_shared(smem);

    float acc[4][4][4] = {};

    // per-lane ldmatrix address components
    const int a_row_l = warp_m * 64 + (lane & 15);
    const int a_col_l = (lane & 16) ? 8 : 0;
    const int b_krow_l = lane & 15;
    const int b_ncol_l = warp_n * 32 + ((lane & 16) ? 8 : 0);

    // Issue async loads for one stage (A 128x32 bf16 + W 32x128 bf16).
    auto issue_stage = [&](int s, int k0) {
        uint32_t abase = smem_b + (uint32_t)s * STG_ELEMS * 2;
#pragma unroll
        for (int r = 0; r < 4; ++r) {
            int idx = tid + r * 256;            // 1024 8B-chunks
            int row = idx >> 3;                 // 0..127
            int c8  = idx & 7;                  // 8B unit within 64B row
            const uint32_t* src = g_Ah + ((size_t)(bm + row) * 512 + (k0 >> 1) + c8 * 2);
            cp_async8(abase + (row * PA + c8 * 4) * 2, src);
        }
        uint32_t wbase = abase + ASZ * 2;
#pragma unroll
        for (int r = 0; r < 4; ++r) {
            int idx = tid + r * 256;
            int kr = idx >> 5;                  // 0..31
            int c8 = idx & 31;                  // 8B unit within 256B row
            const uint32_t* src = g_Wh + ((size_t)(k0 + kr) * 768 + (bn >> 1) + c8 * 2);
            cp_async8(wbase + (kr * PW + c8 * 4) * 2, src);
        }
        CP_COMMIT();
    };

    issue_stage(0, 0);
    issue_stage(1, 32);

    for (int it = 0; it < 32; ++it) {
        const int s = it - (it / 3) * 3;        // it % 3
        CP_WAIT1();
        __syncthreads();
        if (it + 2 < 32) {
            int s2 = (it + 2) - ((it + 2) / 3) * 3;
            issue_stage(s2, (it + 2) * 32);
        } else {
            CP_COMMIT();                         // keep group count uniform
        }

        const uint32_t As_b = smem_b + (uint32_t)s * STG_ELEMS * 2;
        const uint32_t Ws_b = As_b + ASZ * 2;

#pragma unroll
        for (int kk = 0; kk < 32; kk += 16) {
            uint32_t af[4][4];
#pragma unroll
            for (int mt = 0; mt < 4; ++mt) {
                uint32_t addr = As_b + ((a_row_l + mt * 16) * PA + kk + a_col_l) * 2;
                ldsm_x4(af[mt][0], af[mt][1], af[mt][2], af[mt][3], addr);
            }
            uint32_t bf[4][2];
#pragma unroll
            for (int np = 0; np < 2; ++np) {
                uint32_t addr = Ws_b + ((kk + b_krow_l) * PW + b_ncol_l + np * 16) * 2;
                ldsm_x4_t(bf[2 * np][0], bf[2 * np][1],
                          bf[2 * np + 1][0], bf[2 * np + 1][1], addr);
            }
#pragma unroll
            for (int mt = 0; mt < 4; ++mt)
#pragma unroll
                for (int nt = 0; nt < 4; ++nt)
                    mma_bf16(acc[mt][nt], af[mt], bf[nt]);
        }
    }

    // ---- epilogue: bias + RoPE -> bf16 Q/K
    const int g = lane >> 2, t = lane & 3;
    const bool isK = (warp_n >= 2);
    uint32_t* dst = isK ? g_Kh : g_Qh;
    const int dbase = (warp_n & 1) * 32;

    float be[4], bo[4];
    int pi[4];
#pragma unroll
    for (int nt = 0; nt < 4; ++nt) {
        int jb = bn + warp_n * 32 + nt * 8 + 2 * t;
        be[nt] = bias[jb];
        bo[nt] = bias[jb + 1];
        pi[nt] = (dbase + nt * 8 + 2 * t) >> 1;
    }

    const float2* pe2 = (const float2*)pe;

#pragma unroll
    for (int mt = 0; mt < 4; ++mt) {
#pragma unroll
        for (int rr = 0; rr < 2; ++rr) {
            int m = bm + warp_m * 64 + mt * 16 + g + 8 * rr;
            int l = m & 511;
            int b = m >> 9;
            size_t rowbase = ((size_t)(b * 12 + h) * 512 + l) * 32;
#pragma unroll
            for (int nt = 0; nt < 4; ++nt) {
                float2 sc = pe2[l * 32 + pi[nt]];   // x=sin, y=cos
                float e = acc[mt][nt][2 * rr]     + be[nt];
                float o = acc[mt][nt][2 * rr + 1] + bo[nt];
                float re = e * sc.y - o * sc.x;
                float ro = o * sc.y + e * sc.x;
                dst[rowbase + pi[nt]] = pack_bf16x2(re, ro);
            }
        }
    }
}

// ---------------------------------------------------------------------------
// Kernel 2: per (b,h): logits[512,512] = Q @ K^T (bf16 mma), fused mask/tril/scale.
// Block: 128x128 tile, K=64 resident, 256 threads (8 warps 2x4).
// ---------------------------------------------------------------------------
#define PQ 72    // smem pitch (bf16): 144B rows, conflict-free ldmatrix

__global__ __launch_bounds__(256) void qk_logits_kernel(
    const int* __restrict__ mask,   // [16,512]
    float* __restrict__ out)        // [16,12,512,512]
{
    __shared__ __align__(16) uint16_t Qs[128 * PQ];
    __shared__ __align__(16) uint16_t Ks[128 * PQ];

    const int tid = threadIdx.x;
    const int lane = tid & 31;
    const int wid = tid >> 5;
    const int warp_m = wid >> 2;
    const int warp_n = wid & 3;
    const int bh = blockIdx.z;
    const int b  = bh / 12;
    const int bm = blockIdx.y * 128;
    const int bn = blockIdx.x * 128;

    const uint4* Qg = (const uint4*)(g_Qh + ((size_t)bh * 512 + bm) * 32);
    const uint4* Kg = (const uint4*)(g_Kh + ((size_t)bh * 512 + bn) * 32);
#pragma unroll
    for (int r = 0; r < 4; ++r) {
        int chunk = tid + r * 256;
        int row = chunk >> 3;
        int kg  = chunk & 7;
        *(uint4*)&Qs[row * PQ + kg * 8] = Qg[row * 8 + kg];
        *(uint4*)&Ks[row * PQ + kg * 8] = Kg[row * 8 + kg];
    }
    __syncthreads();

    const uint32_t Qs_b = (uint32_t)__cvta_generic_to_shared(Qs);
    const uint32_t Ks_b = (uint32_t)__cvta_generic_to_shared(Ks);

    const int a_row_l = warp_m * 64 + (lane & 15);
    const int a_col_l = (lane & 16) ? 8 : 0;
    const int b_row_l = warp_n * 32 + (lane & 7) + ((lane & 16) >> 1);
    const int b_col_l = (lane & 8) ? 8 : 0;

    float acc[4][4][4] = {};

#pragma unroll
    for (int ks = 0; ks < 4; ++ks) {
        int k = ks * 16;
        uint32_t af[4][4];
#pragma unroll
        for (int mt = 0; mt < 4; ++mt) {
            uint32_t addr = Qs_b + ((a_row_l + mt * 16) * PQ + k + a_col_l) * 2;
            ldsm_x4(af[mt][0], af[mt][1], af[mt][2], af[mt][3], addr);
        }
        uint32_t bf[4][2];
#pragma unroll
        for (int np = 0; np < 2; ++np) {
            uint32_t addr = Ks_b + ((b_row_l + np * 16) * PQ + k + b_col_l) * 2;
            ldsm_x4(bf[2 * np][0], bf[2 * np][1],
                    bf[2 * np + 1][0], bf[2 * np + 1][1], addr);
        }
#pragma unroll
        for (int mt = 0; mt < 4; ++mt)
#pragma unroll
            for (int nt = 0; nt < 4; ++nt)
                mma_bf16(acc[mt][nt], af[mt], bf[nt]);
    }

    // ---- epilogue: padding mask, strict lower-tri, scale 0.125
    const int g = lane >> 2, t = lane & 3;
    const int* mb = mask + b * 512;
    float mv0[4], mv1[4];
    int ncol[4];
#pragma unroll
    for (int nt = 0; nt < 4; ++nt) {
        int n = bn + warp_n * 32 + nt * 8 + 2 * t;
        ncol[nt] = n;
        mv0[nt] = (float)mb[n];
        mv1[nt] = (float)mb[n + 1];
    }

#pragma unroll
    for (int mt = 0; mt < 4; ++mt) {
#pragma unroll
        for (int rr = 0; rr < 2; ++rr) {
            int m = bm + warp_m * 64 + mt * 16 + g + 8 * rr;
            size_t rowbase = ((size_t)bh * 512 + m) * 512;
#pragma unroll
            for (int nt = 0; nt < 4; ++nt) {
                int n = ncol[nt];
                float v0 = acc[mt][nt][2 * rr]     * mv0[nt] - (1.0f - mv0[nt]) * NEG;
                float v1 = acc[mt][nt][2 * rr + 1] * mv1[nt] - (1.0f - mv1[nt]) * NEG;
                if (m > n)     v0 -= NEG;
                if (m > n + 1) v1 -= NEG;
                __stcs((float2*)&out[rowbase + n],
                       make_float2(v0 * 0.125f, v1 * 0.125f));
            }
        }
    }
}

extern "C" void kernel_launch(void* const* d_in, const int* in_sizes, int n_in,
                              void* d_out, int out_size) {
    const float* inputs = (const float*)d_in[0];   // [16,512,1024]
    const int*   mask   = (const int*)d_in[1];     // [16,512]
    const float* W      = (const float*)d_in[2];   // [1024,1536]
    const float* bias   = (const float*)d_in[3];   // [1536]
    const float* pe     = (const float*)d_in[4];   // [512,64]
    float* out = (float*)d_out;                    // [16,12,512,512]

    (void)in_sizes; (void)n_in; (void)out_size;

    // 2,097,152 A float4 + 393,216 W float4 = 2,490,368 -> 9728 blocks exactly
    convert_kernel<<<9728, 256>>>(inputs, W);
    proj_rope_kernel<<<dim3(12, 64), 256>>>(bias, pe);
    qk_logits_kernel<<<dim3(4, 4, 192), 256>>>(mask, out);
}

// round 6
// speedup vs baseline: 5.3447x; 1.0319x over previous
#include <cuda_runtime.h>
#include <cuda_bf16.h>
#include <cstdint>

#define NEG 1000000000000.0f
#define WSCALE 32.0f
#define INV_WSCALE (1.0f / 32.0f)

// Pre-pass outputs.
__device__ uint8_t  g_A8[8192 * 1024];    // A e4m3 [8192][1024], 8 MB
__device__ uint8_t  g_W8T[1536 * 1024];   // (32*W)^T e4m3 [1536][1024], 1.5 MB
// Q/K after projection + RoPE: [bh][l][64] bf16 (bf16x2 words).
__device__ uint32_t g_Qh[192 * 512 * 32];
__device__ uint32_t g_Kh[192 * 512 * 32];

// ---------------------------------------------------------------------------
// helpers
// ---------------------------------------------------------------------------
__device__ __forceinline__ uint32_t pack_bf16x2(float lo, float hi) {
    uint32_t r;
    asm("cvt.rn.bf16x2.f32 %0, %1, %2;" : "=r"(r) : "f"(hi), "f"(lo));
    return r;
}

// pack 4 floats -> 4 e4m3 bytes (ascending byte order = v0..v3)
__device__ __forceinline__ uint32_t pack_e4m3x4(float v0, float v1, float v2, float v3) {
    uint32_t r;
    asm("{\n\t.reg .b16 l, h;\n\t"
        "cvt.rn.satfinite.e4m3x2.f32 l, %2, %1;\n\t"
        "cvt.rn.satfinite.e4m3x2.f32 h, %4, %3;\n\t"
        "mov.b32 %0, {l, h};\n\t}"
        : "=r"(r) : "f"(v0), "f"(v1), "f"(v2), "f"(v3));
    return r;
}

__device__ __forceinline__ uint32_t smem_u32(const void* p) {
    return (uint32_t)__cvta_generic_to_shared(p);
}

__device__ __forceinline__ void cp16(uint32_t dst, const void* src) {
    asm volatile("cp.async.cg.shared.global [%0], [%1], 16;" :: "r"(dst), "l"(src));
}
#define CP_COMMIT() asm volatile("cp.async.commit_group;" ::: "memory")
#define CP_WAIT1()  asm volatile("cp.async.wait_group 1;" ::: "memory")

#define SWZ128(x) ((x) ^ (((x) >> 3) & 0x70))

__device__ __forceinline__ void ldsm_x4(uint32_t& r0, uint32_t& r1,
                                        uint32_t& r2, uint32_t& r3, uint32_t addr) {
    asm volatile("ldmatrix.sync.aligned.m8n8.x4.shared.b16 {%0,%1,%2,%3}, [%4];"
                 : "=r"(r0), "=r"(r1), "=r"(r2), "=r"(r3) : "r"(addr));
}

// fp8 e4m3 mma: D[16x8] += A[16x32] * B[32x8]
__device__ __forceinline__ void mma_fp8(float* c, const uint32_t* a, const uint32_t* b) {
    asm volatile(
        "mma.sync.aligned.m16n8k32.row.col.f32.e4m3.e4m3.f32 "
        "{%0,%1,%2,%3}, {%4,%5,%6,%7}, {%8,%9}, {%0,%1,%2,%3};"
        : "+f"(c[0]), "+f"(c[1]), "+f"(c[2]), "+f"(c[3])
        : "r"(a[0]), "r"(a[1]), "r"(a[2]), "r"(a[3]), "r"(b[0]), "r"(b[1]));
}

// bf16 mma for kernel 2
__device__ __forceinline__ void mma_bf16(float* c, const uint32_t* a, const uint32_t* b) {
    asm volatile(
        "mma.sync.aligned.m16n8k16.row.col.f32.bf16.bf16.f32 "
        "{%0,%1,%2,%3}, {%4,%5,%6,%7}, {%8,%9}, {%0,%1,%2,%3};"
        : "+f"(c[0]), "+f"(c[1]), "+f"(c[2]), "+f"(c[3])
        : "r"(a[0]), "r"(a[1]), "r"(a[2]), "r"(a[3]), "r"(b[0]), "r"(b[1]));
}

// ---------------------------------------------------------------------------
// Pre-pass 1: A fp32 -> e4m3. One thread: 8 floats -> 8 bytes.
// ---------------------------------------------------------------------------
__global__ __launch_bounds__(256) void convertA8_kernel(const float* __restrict__ A) {
    size_t i = (size_t)blockIdx.x * 256 + threadIdx.x;   // < 8192*1024/8
    const float4* p = (const float4*)A + i * 2;
    float4 v0 = p[0], v1 = p[1];
    uint2 u;
    u.x = pack_e4m3x4(v0.x, v0.y, v0.z, v0.w);
    u.y = pack_e4m3x4(v1.x, v1.y, v1.z, v1.w);
    ((uint2*)g_A8)[i] = u;
}

// ---------------------------------------------------------------------------
// Pre-pass 2: W[1024,1536] fp32 -> (32*W)^T [1536,1024] e4m3 (tiled transpose).
// Block: 32 n-cols x 64 k-rows.
// ---------------------------------------------------------------------------
__global__ __launch_bounds__(256) void wtrans8_kernel(const float* __restrict__ W) {
    __shared__ float s[64][33];
    const int tid = threadIdx.x;
    const int n0 = blockIdx.x * 32;
    const int k0 = blockIdx.y * 64;
#pragma unroll
    for (int r = 0; r < 8; ++r) {
        int idx = tid + r * 256;
        int kr = idx >> 5, nc = idx & 31;
        s[kr][nc] = W[(size_t)(k0 + kr) * 1536 + n0 + nc] * WSCALE;
    }
    __syncthreads();
    // each thread: one n-row, 8 k-values -> 8 bytes
    int n = tid >> 3;            // 0..31
    int kc = (tid & 7) * 8;      // 0..56
    uint2 u;
    u.x = pack_e4m3x4(s[kc + 0][n], s[kc + 1][n], s[kc + 2][n], s[kc + 3][n]);
    u.y = pack_e4m3x4(s[kc + 4][n], s[kc + 5][n], s[kc + 6][n], s[kc + 7][n]);
    *(uint2*)&g_W8T[(size_t)(n0 + n) * 1024 + k0 + kc] = u;
}

// ---------------------------------------------------------------------------
// Kernel 1: C[8192,1536] = A @ W + b via fp8 mma.sync (fp32 acc), fused RoPE.
// CTA: 128x128 tile (one head), BK=128 bytes, 3-stage cp.async, 256 threads
// (8 warps, 2(m) x 4(n); warp tile 64x32).
// ---------------------------------------------------------------------------
#define STG8 32768                    // A 16KB + B 16KB per stage
#define K1_SMEM (3 * STG8)

__global__ __launch_bounds__(256) void proj_rope_fp8(
    const float* __restrict__ bias,   // [1536]
    const float* __restrict__ pe)     // [512,64]
{
    extern __shared__ __align__(1024) char smem[];
    const uint32_t db = smem_u32(smem);

    const int tid = threadIdx.x;
    const int lane = tid & 31;
    const int wid = tid >> 5;
    const int warp_m = wid >> 2;      // 0..1
    const int warp_n = wid & 3;       // 0..3
    const int h  = blockIdx.x;        // head 0..11
    const int bn = h * 128;
    const int bm = blockIdx.y * 128;

    float acc[4][4][4] = {};

    // ldmatrix lane addressing (bytes within tile)
    const int a_row_l = warp_m * 64 + (lane & 15);        // + mt*16
    const int a_kb_l  = (lane & 16);                      // 0 or 16 bytes
    const int b_row_l = warp_n * 32 + (lane & 7) + ((lane >> 4) << 3);  // + np*16
    const int b_kb_l  = (lane & 8) << 1;                  // 0 or 16 bytes

    auto issue_load = [&](int s, int k0) {
        const uint32_t ab = db + s * STG8;
#pragma unroll
        for (int r = 0; r < 4; ++r) {
            int idx = tid + r * 256;
            int row = idx >> 3, c = idx & 7;
            cp16(ab + SWZ128(row * 128 + c * 16),
                 g_A8 + (size_t)(bm + row) * 1024 + k0 + c * 16);
        }
        const uint32_t bb = ab + 16384;
#pragma unroll
        for (int r = 0; r < 4; ++r) {
            int idx = tid + r * 256;
            int row = idx >> 3, c = idx & 7;
            cp16(bb + SWZ128(row * 128 + c * 16),
                 g_W8T + (size_t)(bn + row) * 1024 + k0 + c * 16);
        }
        CP_COMMIT();
    };

    issue_load(0, 0);
    issue_load(1, 128);

    for (int it = 0; it < 8; ++it) {
        const int s = it - (it / 3) * 3;        // it % 3
        CP_WAIT1();
        __syncthreads();
        if (it + 2 < 8) {
            int s2 = (it + 2) - ((it + 2) / 3) * 3;
            issue_load(s2, (it + 2) * 128);
        } else {
            CP_COMMIT();
        }

        const uint32_t As_b = db + s * STG8;
        const uint32_t Bs_b = As_b + 16384;

#pragma unroll
        for (int ks = 0; ks < 4; ++ks) {        // 4 ksteps of 32 bytes
            const int kb = ks * 32;
            uint32_t af[4][4];
#pragma unroll
            for (int mt = 0; mt < 4; ++mt) {
                uint32_t addr = As_b + SWZ128((a_row_l + mt * 16) * 128 + kb + a_kb_l);
                ldsm_x4(af[mt][0], af[mt][1], af[mt][2], af[mt][3], addr);
            }
            uint32_t bf[4][2];
#pragma unroll
            for (int np = 0; np < 2; ++np) {
                uint32_t addr = Bs_b + SWZ128((b_row_l + np * 16) * 128 + kb + b_kb_l);
                ldsm_x4(bf[2 * np][0], bf[2 * np][1],
                        bf[2 * np + 1][0], bf[2 * np + 1][1], addr);
            }
#pragma unroll
            for (int mt = 0; mt < 4; ++mt)
#pragma unroll
                for (int nt = 0; nt < 4; ++nt)
                    mma_fp8(acc[mt][nt], af[mt], bf[nt]);
        }
        __syncthreads();
    }

    // ---- epilogue: 1/32 scale + bias + RoPE -> bf16 Q/K
    const int g = lane >> 2, t = lane & 3;
    const int cb = warp_n * 32;               // 0,32,64,96 within head
    const bool isK = (cb >= 64);
    uint32_t* dst = isK ? g_Kh : g_Qh;

    float be[4], bo[4];
    int pi[4];
#pragma unroll
    for (int nt = 0; nt < 4; ++nt) {
        int c = cb + nt * 8 + 2 * t;          // even col within head
        be[nt] = bias[bn + c];
        bo[nt] = bias[bn + c + 1];
        pi[nt] = (c & 63) >> 1;               // RoPE pair index 0..31
    }

    const float2* pe2 = (const float2*)pe;

#pragma unroll
    for (int mt = 0; mt < 4; ++mt) {
#pragma unroll
        for (int rr = 0; rr < 2; ++rr) {
            int m = bm + warp_m * 64 + mt * 16 + g + 8 * rr;
            int l = m & 511;
            int b = m >> 9;
            size_t rowb = ((size_t)(b * 12 + h) * 512 + l) * 32;
#pragma unroll
            for (int nt = 0; nt < 4; ++nt) {
                float2 sc = pe2[l * 32 + pi[nt]];   // x=sin, y=cos
                float e = acc[mt][nt][2 * rr]     * INV_WSCALE + be[nt];
                float o = acc[mt][nt][2 * rr + 1] * INV_WSCALE + bo[nt];
                float re = e * sc.y - o * sc.x;
                float ro = o * sc.y + e * sc.x;
                dst[rowb + pi[nt]] = pack_bf16x2(re, ro);
            }
        }
    }
}

// ---------------------------------------------------------------------------
// Kernel 2: per (b,h): logits = Q @ K^T (bf16 mma.sync), fused mask/tril/scale.
// ---------------------------------------------------------------------------
#define PQ 72

__device__ __forceinline__ void ldsm_x4b(uint32_t& r0, uint32_t& r1,
                                         uint32_t& r2, uint32_t& r3, uint32_t addr) {
    asm volatile("ldmatrix.sync.aligned.m8n8.x4.shared.b16 {%0,%1,%2,%3}, [%4];"
                 : "=r"(r0), "=r"(r1), "=r"(r2), "=r"(r3) : "r"(addr));
}

__global__ __launch_bounds__(256) void qk_logits_kernel(
    const int* __restrict__ mask,   // [16,512]
    float* __restrict__ out)        // [16,12,512,512]
{
    __shared__ __align__(16) uint16_t Qs[128 * PQ];
    __shared__ __align__(16) uint16_t Ks[128 * PQ];

    const int tid = threadIdx.x;
    const int lane = tid & 31;
    const int wid = tid >> 5;
    const int warp_m = wid >> 2;
    const int warp_n = wid & 3;
    const int bh = blockIdx.z;
    const int b  = bh / 12;
    const int bm = blockIdx.y * 128;
    const int bn = blockIdx.x * 128;

    const uint4* Qg = (const uint4*)(g_Qh + ((size_t)bh * 512 + bm) * 32);
    const uint4* Kg = (const uint4*)(g_Kh + ((size_t)bh * 512 + bn) * 32);
#pragma unroll
    for (int r = 0; r < 4; ++r) {
        int chunk = tid + r * 256;
        int row = chunk >> 3;
        int kg  = chunk & 7;
        *(uint4*)&Qs[row * PQ + kg * 8] = Qg[row * 8 + kg];
        *(uint4*)&Ks[row * PQ + kg * 8] = Kg[row * 8 + kg];
    }
    __syncthreads();

    const uint32_t Qs_b = smem_u32(Qs);
    const uint32_t Ks_b = smem_u32(Ks);

    const int a_row_l = warp_m * 64 + (lane & 15);
    const int a_col_l = (lane & 16) ? 8 : 0;
    const int b_row_l = warp_n * 32 + (lane & 7) + ((lane & 16) >> 1);
    const int b_col_l = (lane & 8) ? 8 : 0;

    float acc[4][4][4] = {};

#pragma unroll
    for (int ks = 0; ks < 4; ++ks) {
        int k = ks * 16;
        uint32_t af[4][4];
#pragma unroll
        for (int mt = 0; mt < 4; ++mt) {
            uint32_t addr = Qs_b + ((a_row_l + mt * 16) * PQ + k + a_col_l) * 2;
            ldsm_x4b(af[mt][0], af[mt][1], af[mt][2], af[mt][3], addr);
        }
        uint32_t bf[4][2];
#pragma unroll
        for (int np = 0; np < 2; ++np) {
            uint32_t addr = Ks_b + ((b_row_l + np * 16) * PQ + k + b_col_l) * 2;
            ldsm_x4b(bf[2 * np][0], bf[2 * np][1],
                     bf[2 * np + 1][0], bf[2 * np + 1][1], addr);
        }
#pragma unroll
        for (int mt = 0; mt < 4; ++mt)
#pragma unroll
            for (int nt = 0; nt < 4; ++nt)
                mma_bf16(acc[mt][nt], af[mt], bf[nt]);
    }

    const int g = lane >> 2, t = lane & 3;
    const int* mb = mask + b * 512;
    float mv0[4], mv1[4];
    int ncol[4];
#pragma unroll
    for (int nt = 0; nt < 4; ++nt) {
        int n = bn + warp_n * 32 + nt * 8 + 2 * t;
        ncol[nt] = n;
        mv0[nt] = (float)mb[n];
        mv1[nt] = (float)mb[n + 1];
    }

#pragma unroll
    for (int mt = 0; mt < 4; ++mt) {
#pragma unroll
        for (int rr = 0; rr < 2; ++rr) {
            int m = bm + warp_m * 64 + mt * 16 + g + 8 * rr;
            size_t rowbase = ((size_t)bh * 512 + m) * 512;
#pragma unroll
            for (int nt = 0; nt < 4; ++nt) {
                int n = ncol[nt];
                float v0 = acc[mt][nt][2 * rr]     * mv0[nt] - (1.0f - mv0[nt]) * NEG;
                float v1 = acc[mt][nt][2 * rr + 1] * mv1[nt] - (1.0f - mv1[nt]) * NEG;
                if (m > n)     v0 -= NEG;
                if (m > n + 1) v1 -= NEG;
                __stcs((float2*)&out[rowbase + n],
                       make_float2(v0 * 0.125f, v1 * 0.125f));
            }
        }
    }
}

extern "C" void kernel_launch(void* const* d_in, const int* in_sizes, int n_in,
                              void* d_out, int out_size) {
    const float* inputs = (const float*)d_in[0];   // [16,512,1024]
    const int*   mask   = (const int*)d_in[1];     // [16,512]
    const float* W      = (const float*)d_in[2];   // [1024,1536]
    const float* bias   = (const float*)d_in[3];   // [1536]
    const float* pe     = (const float*)d_in[4];   // [512,64]
    float* out = (float*)d_out;                    // [16,12,512,512]

    (void)in_sizes; (void)n_in; (void)out_size;

    cudaFuncSetAttribute(proj_rope_fp8,
                         cudaFuncAttributeMaxDynamicSharedMemorySize, K1_SMEM);

    convertA8_kernel<<<4096, 256>>>(inputs);           // 8192*1024/8 threads
    wtrans8_kernel<<<dim3(48, 16), 256>>>(W);
    proj_rope_fp8<<<dim3(12, 64), 256, K1_SMEM>>>(bias, pe);
    qk_logits_kernel<<<dim3(4, 4, 192), 256>>>(mask, out);
}